// round 12
// baseline (speedup 1.0000x reference)
#include <cuda_runtime.h>
#include <cuda_bf16.h>
#include <cuda_fp16.h>
#include <cfloat>
#include <cstdint>

#define N_NODES 50000
#define N_EDGES 800000
#define HID 64
#define ZDIM 320
#define WSTRIDE 68                 // padded W row (64x68, zeros in pad)
#define WSZ (64 * WSTRIDE)
#define SCAN_BLK 98                // ceil(50000/512)

typedef unsigned long long ull;
typedef uint32_t u32;

// ---------------- device scratch ----------------
__device__ __half g_uh[N_NODES * HID];     // u stored fp16 (gather payload)
__device__ float g_z[N_NODES * ZDIM];
__device__ int   g_cnt[N_NODES];           // INVARIANT: all-zero at kernel_launch entry
__device__ int   g_off[N_NODES + 1];
__device__ int   g_cur[N_NODES];
__device__ int   g_csr[N_EDGES];
__device__ int   g_bsum[SCAN_BLK];
__device__ float g_Wq[5 * WSZ];            // all 5 quantized layer weights
__device__ __half g_w1h[128 * 320], g_w1l[128 * 320];   // fp16 hi/lo split MLP weights
__device__ __half g_w2h[128 * 128], g_w2l[128 * 128];
__device__ __half g_w3h[64 * 128],  g_w3l[64 * 128];

// ---------------- f32x2 helpers ----------------
__device__ __forceinline__ ull fma2(ull a, ull b, ull c) {
    ull d;
    asm("fma.rn.f32x2 %0, %1, %2, %3;" : "=l"(d) : "l"(a), "l"(b), "l"(c));
    return d;
}
__device__ __forceinline__ float sum2(ull a) {
    float lo, hi;
    asm("mov.b64 {%0, %1}, %2;" : "=f"(lo), "=f"(hi) : "l"(a));
    return lo + hi;
}

// ---------------- mma.sync m16n8k16 f16 helper ----------------
__device__ __forceinline__ void mma16816(float* d, u32 a0, u32 a1, u32 a2, u32 a3,
                                         u32 b0, u32 b1) {
    asm volatile(
        "mma.sync.aligned.m16n8k16.row.col.f32.f16.f16.f32 "
        "{%0,%1,%2,%3}, {%4,%5,%6,%7}, {%8,%9}, {%0,%1,%2,%3};"
        : "+f"(d[0]), "+f"(d[1]), "+f"(d[2]), "+f"(d[3])
        : "r"(a0), "r"(a1), "r"(a2), "r"(a3), "r"(b0), "r"(b1));
}

// ---------------- CSR construction ----------------
__global__ void k_hist(const int* __restrict__ ei) {
    int e = blockIdx.x * blockDim.x + threadIdx.x;
    if (e < N_EDGES) atomicAdd(&g_cnt[ei[N_EDGES + e]], 1);
}

__global__ void k_scan_local() {
    __shared__ int wsums[16];
    int b = blockIdx.x, tid = threadIdx.x, lane = tid & 31, wid = tid >> 5;
    int i = b * 512 + tid;
    int v = (i < N_NODES) ? g_cnt[i] : 0;
    int x = v;
    #pragma unroll
    for (int o = 1; o < 32; o <<= 1) {
        int y = __shfl_up_sync(0xffffffffu, x, o);
        if (lane >= o) x += y;
    }
    if (lane == 31) wsums[wid] = x;
    __syncthreads();
    if (wid == 0 && lane < 16) {
        int w = wsums[lane];
        int xs = w;
        #pragma unroll
        for (int o = 1; o < 16; o <<= 1) {
            int y = __shfl_up_sync(0xffffu, xs, o);
            if (lane >= o) xs += y;
        }
        wsums[lane] = xs - w;
    }
    __syncthreads();
    int excl = x - v + wsums[wid];
    if (i < N_NODES) g_off[i] = excl;
    if (tid == 511) g_bsum[b] = excl + v;
}

__global__ void k_scan_add() {
    __shared__ int part[4];
    int b = blockIdx.x, tid = threadIdx.x, lane = tid & 31, wid = tid >> 5;
    int v = 0;
    if (tid < b) v = g_bsum[tid];      // b <= 97 < 128
    if (tid < 128) {
        #pragma unroll
        for (int o = 16; o > 0; o >>= 1) v += __shfl_xor_sync(0xffffffffu, v, o);
        if (lane == 0) part[wid] = v;
    }
    __syncthreads();
    int add = part[0] + part[1] + part[2] + part[3];
    int i = b * 512 + tid;
    if (i < N_NODES) {
        int o = g_off[i] + add;
        g_off[i] = o;
        g_cur[i] = o;
        g_cnt[i] = 0;   // restore zero-invariant for next replay
    }
    if (i == 0) g_off[N_NODES] = N_EDGES;
}

__global__ void k_scatter(const int* __restrict__ ei) {
    int e = blockIdx.x * blockDim.x + threadIdx.x;
    if (e < N_EDGES) {
        int d = ei[N_EDGES + e];
        int p = atomicAdd(&g_cur[d], 1);
        g_csr[p] = ei[e];
    }
}

// ---------------- weight prep (fake-quant + fp16 hi/lo split of MLP weights) ----------------
__global__ void k_quant_prep(const float* __restrict__ W0, const float* __restrict__ Ws,
                             const float* __restrict__ w1, const float* __restrict__ w2,
                             const float* __restrict__ w3) {
    int b = blockIdx.x, tid = threadIdx.x;
    if (b < 5) {
        __shared__ float red[256];
        const float* W = (b == 0) ? W0 : (Ws + (size_t)(b - 1) * 64 * 67);
        int cols = (b == 0) ? 4 : 67;
        int n = 64 * cols;
        float* dst = g_Wq + b * WSZ;

        float m = 0.f;
        for (int i = tid; i < n; i += 256) m = fmaxf(m, fabsf(W[i]));
        red[tid] = m;
        __syncthreads();
        for (int s = 128; s > 0; s >>= 1) {
            if (tid < s) red[tid] = fmaxf(red[tid], red[tid + s]);
            __syncthreads();
        }
        float sc = fmaxf(red[0] * (1.0f / 127.0f), 1e-8f);
        for (int i = tid; i < WSZ; i += 256) dst[i] = 0.0f;
        __syncthreads();
        for (int i = tid; i < n; i += 256) {
            int k = i / cols, c = i % cols;
            float q = rintf(W[i] / sc);
            q = fminf(fmaxf(q, -127.0f), 127.0f) * sc;
            dst[k * WSTRIDE + c] = q;
        }
    } else {
        int i = (b - 5) * 256 + tid;
        if (i < 40960) {
            float v = w1[i];
            __half h = __float2half(v);
            g_w1h[i] = h;
            g_w1l[i] = __float2half(v - __half2float(h));
        }
        if (i < 16384) {
            float v = w2[i];
            __half h = __float2half(v);
            g_w2h[i] = h;
            g_w2l[i] = __float2half(v - __half2float(h));
        }
        if (i < 8192) {
            float v = w3[i];
            __half h = __float2half(v);
            g_w3h[i] = h;
            g_w3l[i] = __float2half(v - __half2float(h));
        }
    }
}

// ---------------- layer-0 transform ----------------
__global__ __launch_bounds__(256) void k_transform0(const float* __restrict__ x,
                                                    const float* __restrict__ pos) {
    __shared__ float4 Wsh[64];
    __shared__ float  xs[32];
    __shared__ float  ps[96];
    int tid = threadIdx.x;
    int nbase = blockIdx.x * 32;
    if (tid < 64) {
        const float* wr = g_Wq + tid * WSTRIDE;
        Wsh[tid] = make_float4(wr[0], wr[1], wr[2], wr[3]);
    } else if (tid < 96) {
        int n = nbase + (tid - 64);
        xs[tid - 64] = (n < N_NODES) ? x[n] : 0.f;
    } else if (tid < 192) {
        int j = tid - 96;
        int gi = nbase * 3 + j;
        ps[j] = (gi < N_NODES * 3) ? pos[gi] : 0.f;
    }
    __syncthreads();
    int k = tid & 63, grp = tid >> 6;
    float4 w = Wsh[k];
    #pragma unroll
    for (int j = 0; j < 8; j++) {
        int nn = grp * 8 + j;
        int n = nbase + nn;
        if (n < N_NODES) {
            float r = w.x * xs[nn] + w.y * ps[3 * nn] + w.z * ps[3 * nn + 1] + w.w * ps[3 * nn + 2];
            g_uh[(size_t)n * HID + k] = __float2half(r);
        }
    }
}

// ---------------- layers 1-4 transform ----------------
__global__ __launch_bounds__(256) void k_transform(const float* __restrict__ pos, int layer) {
    constexpr int C4 = 17;
    __shared__ float Wsh[WSZ];
    __shared__ float fsh[32][WSTRIDE];
    int tid = threadIdx.x;
    int k = tid & 63, grp = tid >> 6;
    const float* Wsrc = g_Wq + layer * WSZ;
    {
        const float4* s4 = (const float4*)Wsrc;
        float4* d4 = (float4*)Wsh;
        #pragma unroll
        for (int i = tid; i < WSZ / 4; i += 256) d4[i] = s4[i];
    }
    int nbase = blockIdx.x * 32;
    const float* h = g_z + (size_t)(layer - 1) * HID;
    #pragma unroll
    for (int i = tid; i < 32 * 64; i += 256) {
        int nn = i >> 6, c = i & 63;
        int gn = nbase + nn;
        fsh[nn][c] = (gn < N_NODES) ? h[(size_t)gn * ZDIM + c] : 0.f;
    }
    if (tid < 128) {
        int nn = tid >> 2, j = tid & 3;
        int gn = nbase + nn;
        float v = 0.f;
        if (j < 3 && gn < N_NODES) v = pos[gn * 3 + j];
        fsh[nn][64 + j] = v;
    }
    __syncthreads();
    ull w2r[C4 * 2];
    #pragma unroll
    for (int c4 = 0; c4 < C4; c4++) {
        ulonglong2 wv = *(const ulonglong2*)&Wsh[k * WSTRIDE + 4 * c4];
        w2r[2 * c4] = wv.x; w2r[2 * c4 + 1] = wv.y;
    }
    ull acc[8];
    #pragma unroll
    for (int j = 0; j < 8; j++) acc[j] = 0;
    #pragma unroll
    for (int c4 = 0; c4 < C4; c4++) {
        ull w01 = w2r[2 * c4], w23 = w2r[2 * c4 + 1];
        #pragma unroll
        for (int j = 0; j < 8; j++) {
            ulonglong2 f = *(const ulonglong2*)&fsh[grp * 8 + j][4 * c4];
            acc[j] = fma2(f.x, w01, acc[j]);
            acc[j] = fma2(f.y, w23, acc[j]);
        }
    }
    #pragma unroll
    for (int j = 0; j < 8; j++) {
        int n = nbase + grp * 8 + j;
        if (n < N_NODES) g_uh[(size_t)n * HID + k] = __float2half(sum2(acc[j]));
    }
}

// ---------------- aggregation: 2 nodes/warp, 16 lanes x half2x2 (8B/lane) ----------------
__global__ __launch_bounds__(256) void k_aggregate(const float* __restrict__ pos,
                                                   const float* __restrict__ ln_g,
                                                   const float* __restrict__ ln_b,
                                                   int layer, int cols) {
    __shared__ float Wp[64][3];
    __shared__ float gs[64], bs[64];
    int tid = threadIdx.x;
    if (tid < 64) { gs[tid] = ln_g[layer * 64 + tid]; bs[tid] = ln_b[layer * 64 + tid]; }
    const float* Wsrc = g_Wq + layer * WSZ;
    for (int i = tid; i < 192; i += 256) {
        int k = i / 3, j = i % 3;
        Wp[k][j] = Wsrc[k * WSTRIDE + (cols - 3) + j];
    }
    __syncthreads();

    int wid = tid >> 5, lane = tid & 31;
    int half = lane >> 4, l16 = lane & 15;
    int n = blockIdx.x * 16 + wid * 2 + half;
    int s = g_off[n], e = g_off[n + 1];
    const uint2* ubase = (const uint2*)g_uh;

    __half2 M0 = __float2half2_rn(-65504.f);
    __half2 M1 = __float2half2_rn(-65504.f);
    int p = s;
    for (; p + 8 <= e; p += 8) {
        int i0 = g_csr[p],     i1 = g_csr[p + 1], i2 = g_csr[p + 2], i3 = g_csr[p + 3];
        int i4 = g_csr[p + 4], i5 = g_csr[p + 5], i6 = g_csr[p + 6], i7 = g_csr[p + 7];
        uint2 a = __ldcg(&ubase[(size_t)i0 * 16 + l16]);
        uint2 b = __ldcg(&ubase[(size_t)i1 * 16 + l16]);
        uint2 c = __ldcg(&ubase[(size_t)i2 * 16 + l16]);
        uint2 d = __ldcg(&ubase[(size_t)i3 * 16 + l16]);
        uint2 f = __ldcg(&ubase[(size_t)i4 * 16 + l16]);
        uint2 g = __ldcg(&ubase[(size_t)i5 * 16 + l16]);
        uint2 h = __ldcg(&ubase[(size_t)i6 * 16 + l16]);
        uint2 q = __ldcg(&ubase[(size_t)i7 * 16 + l16]);
        M0 = __hmax2(M0, __hmax2(__hmax2(*(__half2*)&a.x, *(__half2*)&b.x),
                                 __hmax2(*(__half2*)&c.x, *(__half2*)&d.x)));
        M0 = __hmax2(M0, __hmax2(__hmax2(*(__half2*)&f.x, *(__half2*)&g.x),
                                 __hmax2(*(__half2*)&h.x, *(__half2*)&q.x)));
        M1 = __hmax2(M1, __hmax2(__hmax2(*(__half2*)&a.y, *(__half2*)&b.y),
                                 __hmax2(*(__half2*)&c.y, *(__half2*)&d.y)));
        M1 = __hmax2(M1, __hmax2(__hmax2(*(__half2*)&f.y, *(__half2*)&g.y),
                                 __hmax2(*(__half2*)&h.y, *(__half2*)&q.y)));
    }
    for (; p + 4 <= e; p += 4) {
        int i0 = g_csr[p], i1 = g_csr[p + 1], i2 = g_csr[p + 2], i3 = g_csr[p + 3];
        uint2 a = __ldcg(&ubase[(size_t)i0 * 16 + l16]);
        uint2 b = __ldcg(&ubase[(size_t)i1 * 16 + l16]);
        uint2 c = __ldcg(&ubase[(size_t)i2 * 16 + l16]);
        uint2 d = __ldcg(&ubase[(size_t)i3 * 16 + l16]);
        M0 = __hmax2(M0, __hmax2(__hmax2(*(__half2*)&a.x, *(__half2*)&b.x),
                                 __hmax2(*(__half2*)&c.x, *(__half2*)&d.x)));
        M1 = __hmax2(M1, __hmax2(__hmax2(*(__half2*)&a.y, *(__half2*)&b.y),
                                 __hmax2(*(__half2*)&c.y, *(__half2*)&d.y)));
    }
    for (; p < e; p++) {
        int i0 = g_csr[p];
        uint2 a = __ldcg(&ubase[(size_t)i0 * 16 + l16]);
        M0 = __hmax2(M0, *(__half2*)&a.x);
        M1 = __hmax2(M1, *(__half2*)&a.y);
    }

    float2 f0 = __half22float2(M0);
    float2 f1 = __half22float2(M1);

    float px = pos[n * 3 + 0], py = pos[n * 3 + 1], pz = pos[n * 3 + 2];
    int k0 = 4 * l16;
    float4 hh = make_float4(0.f, 0.f, 0.f, 0.f);
    if (e > s) {
        hh.x = f0.x - (px * Wp[k0 + 0][0] + py * Wp[k0 + 0][1] + pz * Wp[k0 + 0][2]);
        hh.y = f0.y - (px * Wp[k0 + 1][0] + py * Wp[k0 + 1][1] + pz * Wp[k0 + 1][2]);
        hh.z = f1.x - (px * Wp[k0 + 2][0] + py * Wp[k0 + 2][1] + pz * Wp[k0 + 2][2]);
        hh.w = f1.y - (px * Wp[k0 + 3][0] + py * Wp[k0 + 3][1] + pz * Wp[k0 + 3][2]);
    }

    float sum = hh.x + hh.y + hh.z + hh.w;
    float sq  = hh.x * hh.x + hh.y * hh.y + hh.z * hh.z + hh.w * hh.w;
    #pragma unroll
    for (int o = 8; o > 0; o >>= 1) {
        sum += __shfl_xor_sync(0xffffffffu, sum, o);
        sq  += __shfl_xor_sync(0xffffffffu, sq, o);
    }
    float mean = sum * (1.0f / 64.0f);
    float var  = fmaxf(sq * (1.0f / 64.0f) - mean * mean, 0.f);
    float rstd = rsqrtf(var + 1e-5f);
    float4 o4;
    o4.x = fmaxf((hh.x - mean) * rstd * gs[k0 + 0] + bs[k0 + 0], 0.f);
    o4.y = fmaxf((hh.y - mean) * rstd * gs[k0 + 1] + bs[k0 + 1], 0.f);
    o4.z = fmaxf((hh.z - mean) * rstd * gs[k0 + 2] + bs[k0 + 2], 0.f);
    o4.w = fmaxf((hh.w - mean) * rstd * gs[k0 + 3] + bs[k0 + 3], 0.f);
    *(float4*)&g_z[(size_t)n * ZDIM + layer * 64 + k0] = o4;
}

// ---------------- MLP via HMMA (mma.sync m16n8k16, fp16 hi/lo split) ----------------
// dyn smem layout (bytes):
#define OZ32 0              // f32 [16][320]        20480
#define OZH  20480          // half [16][328]       10496
#define OZL  30976          // half [16][328]       10496
#define OH1H 41472          // half [16][136]        4352
#define OH1L 45824
#define OH2H 50176
#define OH2L 54528
#define OH3  58880          // f32 [16][64]          4096
#define OST  62976          // f32 mean[16], rstd[16] 128
#define SMEM_MLP 63104

__global__ __launch_bounds__(128) void k_mlp(const float* __restrict__ b1,
                                             const float* __restrict__ b2,
                                             const float* __restrict__ b3,
                                             const float* __restrict__ w4,
                                             const float* __restrict__ b4,
                                             const float* __restrict__ scale,
                                             float* __restrict__ out) {
    extern __shared__ char sm[];
    float*  zsh = (float*)(sm + OZ32);
    __half* zh  = (__half*)(sm + OZH);
    __half* zl  = (__half*)(sm + OZL);
    __half* h1h = (__half*)(sm + OH1H);
    __half* h1l = (__half*)(sm + OH1L);
    __half* h2h = (__half*)(sm + OH2H);
    __half* h2l = (__half*)(sm + OH2L);
    float*  h3s = (float*)(sm + OH3);
    float*  meansh = (float*)(sm + OST);
    float*  rstdsh = (float*)(sm + OST + 64);

    int tid = threadIdx.x;
    int n0 = blockIdx.x * 16;
    int warp = tid >> 5, lane = tid & 31;
    int g = lane >> 2, tq = lane & 3;

    for (int i = tid; i < 16 * 320; i += 128) zsh[i] = g_z[(size_t)n0 * ZDIM + i];
    __syncthreads();

    // LayerNorm(320), g=1 b=0
    {
        int node = tid >> 3, j = tid & 7;
        float s = 0.f, sq = 0.f;
        for (int c = j; c < 320; c += 8) {
            float v = zsh[node * 320 + c];
            s += v; sq += v * v;
        }
        #pragma unroll
        for (int o = 4; o > 0; o >>= 1) {
            s  += __shfl_down_sync(0xffffffffu, s, o, 8);
            sq += __shfl_down_sync(0xffffffffu, sq, o, 8);
        }
        if (j == 0) {
            float mean = s * (1.0f / 320.0f);
            float var  = fmaxf(sq * (1.0f / 320.0f) - mean * mean, 0.f);
            meansh[node] = mean;
            rstdsh[node] = rsqrtf(var + 1e-5f);
        }
    }
    __syncthreads();
    // normalize + split into fp16 hi/lo
    for (int i = tid; i < 16 * 320; i += 128) {
        int nn = i / 320, c = i - nn * 320;
        float v = (zsh[i] - meansh[nn]) * rstdsh[nn];
        __half h = __float2half(v);
        zh[nn * 328 + c] = h;
        zl[nn * 328 + c] = __float2half(v - __half2float(h));
    }
    __syncthreads();

    float d[4][4];

    // ---- layer 1: 320 -> 128 (4 n-tiles/warp, K=320) ----
    #pragma unroll
    for (int t = 0; t < 4; t++) { d[t][0] = d[t][1] = d[t][2] = d[t][3] = 0.f; }
    for (int kt = 0; kt < 20; kt++) {
        int k0 = kt * 16;
        u32 ah0 = *(const u32*)&zh[g * 328 + k0 + tq * 2];
        u32 ah1 = *(const u32*)&zh[(g + 8) * 328 + k0 + tq * 2];
        u32 ah2 = *(const u32*)&zh[g * 328 + k0 + 8 + tq * 2];
        u32 ah3 = *(const u32*)&zh[(g + 8) * 328 + k0 + 8 + tq * 2];
        u32 al0 = *(const u32*)&zl[g * 328 + k0 + tq * 2];
        u32 al1 = *(const u32*)&zl[(g + 8) * 328 + k0 + tq * 2];
        u32 al2 = *(const u32*)&zl[g * 328 + k0 + 8 + tq * 2];
        u32 al3 = *(const u32*)&zl[(g + 8) * 328 + k0 + 8 + tq * 2];
        #pragma unroll
        for (int t = 0; t < 4; t++) {
            int n = warp * 32 + t * 8 + g;
            u32 bh0 = __ldg((const u32*)&g_w1h[n * 320 + k0 + tq * 2]);
            u32 bh1 = __ldg((const u32*)&g_w1h[n * 320 + k0 + 8 + tq * 2]);
            u32 bl0 = __ldg((const u32*)&g_w1l[n * 320 + k0 + tq * 2]);
            u32 bl1 = __ldg((const u32*)&g_w1l[n * 320 + k0 + 8 + tq * 2]);
            mma16816(d[t], ah0, ah1, ah2, ah3, bh0, bh1);
            mma16816(d[t], ah0, ah1, ah2, ah3, bl0, bl1);
            mma16816(d[t], al0, al1, al2, al3, bh0, bh1);
        }
    }
    #pragma unroll
    for (int t = 0; t < 4; t++) {
        int col = warp * 32 + t * 8 + tq * 2;
        float bb0 = b1[col], bb1 = b1[col + 1];
        float v00 = fmaxf(d[t][0] + bb0, 0.f), v01 = fmaxf(d[t][1] + bb1, 0.f);
        float v10 = fmaxf(d[t][2] + bb0, 0.f), v11 = fmaxf(d[t][3] + bb1, 0.f);
        __half x;
        x = __float2half(v00); h1h[g * 136 + col] = x; h1l[g * 136 + col] = __float2half(v00 - __half2float(x));
        x = __float2half(v01); h1h[g * 136 + col + 1] = x; h1l[g * 136 + col + 1] = __float2half(v01 - __half2float(x));
        x = __float2half(v10); h1h[(g + 8) * 136 + col] = x; h1l[(g + 8) * 136 + col] = __float2half(v10 - __half2float(x));
        x = __float2half(v11); h1h[(g + 8) * 136 + col + 1] = x; h1l[(g + 8) * 136 + col + 1] = __float2half(v11 - __half2float(x));
    }
    __syncthreads();

    // ---- layer 2: 128 -> 128 (4 n-tiles/warp, K=128) ----
    #pragma unroll
    for (int t = 0; t < 4; t++) { d[t][0] = d[t][1] = d[t][2] = d[t][3] = 0.f; }
    for (int kt = 0; kt < 8; kt++) {
        int k0 = kt * 16;
        u32 ah0 = *(const u32*)&h1h[g * 136 + k0 + tq * 2];
        u32 ah1 = *(const u32*)&h1h[(g + 8) * 136 + k0 + tq * 2];
        u32 ah2 = *(const u32*)&h1h[g * 136 + k0 + 8 + tq * 2];
        u32 ah3 = *(const u32*)&h1h[(g + 8) * 136 + k0 + 8 + tq * 2];
        u32 al0 = *(const u32*)&h1l[g * 136 + k0 + tq * 2];
        u32 al1 = *(const u32*)&h1l[(g + 8) * 136 + k0 + tq * 2];
        u32 al2 = *(const u32*)&h1l[g * 136 + k0 + 8 + tq * 2];
        u32 al3 = *(const u32*)&h1l[(g + 8) * 136 + k0 + 8 + tq * 2];
        #pragma unroll
        for (int t = 0; t < 4; t++) {
            int n = warp * 32 + t * 8 + g;
            u32 bh0 = __ldg((const u32*)&g_w2h[n * 128 + k0 + tq * 2]);
            u32 bh1 = __ldg((const u32*)&g_w2h[n * 128 + k0 + 8 + tq * 2]);
            u32 bl0 = __ldg((const u32*)&g_w2l[n * 128 + k0 + tq * 2]);
            u32 bl1 = __ldg((const u32*)&g_w2l[n * 128 + k0 + 8 + tq * 2]);
            mma16816(d[t], ah0, ah1, ah2, ah3, bh0, bh1);
            mma16816(d[t], ah0, ah1, ah2, ah3, bl0, bl1);
            mma16816(d[t], al0, al1, al2, al3, bh0, bh1);
        }
    }
    #pragma unroll
    for (int t = 0; t < 4; t++) {
        int col = warp * 32 + t * 8 + tq * 2;
        float bb0 = b2[col], bb1 = b2[col + 1];
        float v00 = fmaxf(d[t][0] + bb0, 0.f), v01 = fmaxf(d[t][1] + bb1, 0.f);
        float v10 = fmaxf(d[t][2] + bb0, 0.f), v11 = fmaxf(d[t][3] + bb1, 0.f);
        __half x;
        x = __float2half(v00); h2h[g * 136 + col] = x; h2l[g * 136 + col] = __float2half(v00 - __half2float(x));
        x = __float2half(v01); h2h[g * 136 + col + 1] = x; h2l[g * 136 + col + 1] = __float2half(v01 - __half2float(x));
        x = __float2half(v10); h2h[(g + 8) * 136 + col] = x; h2l[(g + 8) * 136 + col] = __float2half(v10 - __half2float(x));
        x = __float2half(v11); h2h[(g + 8) * 136 + col + 1] = x; h2l[(g + 8) * 136 + col + 1] = __float2half(v11 - __half2float(x));
    }
    __syncthreads();

    // ---- layer 3: 128 -> 64 (2 n-tiles/warp, K=128) ----
    #pragma unroll
    for (int t = 0; t < 2; t++) { d[t][0] = d[t][1] = d[t][2] = d[t][3] = 0.f; }
    for (int kt = 0; kt < 8; kt++) {
        int k0 = kt * 16;
        u32 ah0 = *(const u32*)&h2h[g * 136 + k0 + tq * 2];
        u32 ah1 = *(const u32*)&h2h[(g + 8) * 136 + k0 + tq * 2];
        u32 ah2 = *(const u32*)&h2h[g * 136 + k0 + 8 + tq * 2];
        u32 ah3 = *(const u32*)&h2h[(g + 8) * 136 + k0 + 8 + tq * 2];
        u32 al0 = *(const u32*)&h2l[g * 136 + k0 + tq * 2];
        u32 al1 = *(const u32*)&h2l[(g + 8) * 136 + k0 + tq * 2];
        u32 al2 = *(const u32*)&h2l[g * 136 + k0 + 8 + tq * 2];
        u32 al3 = *(const u32*)&h2l[(g + 8) * 136 + k0 + 8 + tq * 2];
        #pragma unroll
        for (int t = 0; t < 2; t++) {
            int n = warp * 16 + t * 8 + g;
            u32 bh0 = __ldg((const u32*)&g_w3h[n * 128 + k0 + tq * 2]);
            u32 bh1 = __ldg((const u32*)&g_w3h[n * 128 + k0 + 8 + tq * 2]);
            u32 bl0 = __ldg((const u32*)&g_w3l[n * 128 + k0 + tq * 2]);
            u32 bl1 = __ldg((const u32*)&g_w3l[n * 128 + k0 + 8 + tq * 2]);
            mma16816(d[t], ah0, ah1, ah2, ah3, bh0, bh1);
            mma16816(d[t], ah0, ah1, ah2, ah3, bl0, bl1);
            mma16816(d[t], al0, al1, al2, al3, bh0, bh1);
        }
    }
    #pragma unroll
    for (int t = 0; t < 2; t++) {
        int col = warp * 16 + t * 8 + tq * 2;
        float bb0 = b3[col], bb1 = b3[col + 1];
        h3s[g * 64 + col]           = fmaxf(d[t][0] + bb0, 0.f);
        h3s[g * 64 + col + 1]       = fmaxf(d[t][1] + bb1, 0.f);
        h3s[(g + 8) * 64 + col]     = fmaxf(d[t][2] + bb0, 0.f);
        h3s[(g + 8) * 64 + col + 1] = fmaxf(d[t][3] + bb1, 0.f);
    }
    __syncthreads();

    // ---- layer 4: 64 -> 2, * scale ----
    if (tid < 32) {
        int nn = tid >> 1, o = tid & 1;
        float a = b4[o];
        const float* wrow = &w4[o * 64];
        #pragma unroll 8
        for (int c = 0; c < 64; c++) a += h3s[nn * 64 + c] * wrow[c];
        out[(size_t)(n0 + nn) * 2 + o] = a * scale[o];
    }
}

// ---------------- launch ----------------
extern "C" void kernel_launch(void* const* d_in, const int* in_sizes, int n_in,
                              void* d_out, int out_size) {
    const float* x     = (const float*)d_in[0];
    const float* pos   = (const float*)d_in[1];
    const int*   ei    = (const int*)d_in[2];
    const float* W0    = (const float*)d_in[3];
    const float* Ws    = (const float*)d_in[4];
    const float* ln_g  = (const float*)d_in[5];
    const float* ln_b  = (const float*)d_in[6];
    const float* w1    = (const float*)d_in[7];
    const float* b1    = (const float*)d_in[8];
    const float* w2    = (const float*)d_in[9];
    const float* b2    = (const float*)d_in[10];
    const float* w3    = (const float*)d_in[11];
    const float* b3    = (const float*)d_in[12];
    const float* w4    = (const float*)d_in[13];
    const float* b4    = (const float*)d_in[14];
    const float* scale = (const float*)d_in[15];
    float* out = (float*)d_out;

    cudaFuncSetAttribute(k_mlp, cudaFuncAttributeMaxDynamicSharedMemorySize, SMEM_MLP);

    const int TGRID = (N_NODES + 31) / 32;  // 1563

    k_hist<<<(N_EDGES + 255) / 256, 256>>>(ei);                    // #1
    k_quant_prep<<<165, 256>>>(W0, Ws, w1, w2, w3);                // #2
    k_scan_local<<<SCAN_BLK, 512>>>();                             // #3
    k_transform0<<<TGRID, 256>>>(x, pos);                          // #4  <- profiled
    k_scan_add<<<SCAN_BLK, 512>>>();                               // #5
    k_scatter<<<(N_EDGES + 255) / 256, 256>>>(ei);                 // #6
    k_aggregate<<<N_NODES / 16, 256>>>(pos, ln_g, ln_b, 0, 4);     // #7

    for (int i = 1; i < 5; i++) {
        k_transform<<<TGRID, 256>>>(pos, i);
        k_aggregate<<<N_NODES / 16, 256>>>(pos, ln_g, ln_b, i, 67);
    }

    k_mlp<<<N_NODES / 16, 128, SMEM_MLP>>>(b1, b2, b3, w4, b4, scale, out);
}

// round 13
// speedup vs baseline: 1.0840x; 1.0840x over previous
#include <cuda_runtime.h>
#include <cuda_bf16.h>
#include <cuda_fp16.h>
#include <cfloat>
#include <cstdint>

#define N_NODES 50000
#define N_EDGES 800000
#define HID 64
#define ZDIM 320
#define WSTRIDE 68                 // padded W row (64x68, zeros in pad)
#define WSZ (64 * WSTRIDE)
#define SCAN_BLK 98                // ceil(50000/512)

typedef unsigned long long ull;
typedef uint32_t u32;

// ---------------- device scratch ----------------
__device__ __half g_uh[N_NODES * HID];     // u stored fp16 (gather payload)
__device__ float g_z[N_NODES * ZDIM];
__device__ int   g_cnt[N_NODES];           // INVARIANT: all-zero at kernel_launch entry
__device__ int   g_off[N_NODES + 1];
__device__ int   g_cur[N_NODES];
__device__ int   g_csr[N_EDGES];
__device__ int   g_bsum[SCAN_BLK];
__device__ float g_Wq[5 * WSZ];            // all 5 quantized layer weights
// HMMA fragment-ordered weights (hi/lo fp16 split):
// index = (kt * NB + nb) * 32 + lane ; uint2 = {B[k0+tq*2..+1|col], B[k0+8+tq*2..+1|col]}
__device__ uint2 g_w1f_h[20 * 16 * 32], g_w1f_l[20 * 16 * 32];   // 320->128
__device__ uint2 g_w2f_h[8 * 16 * 32],  g_w2f_l[8 * 16 * 32];    // 128->128
__device__ uint2 g_w3f_h[8 * 8 * 32],   g_w3f_l[8 * 8 * 32];     // 128->64

// ---------------- f32x2 helpers ----------------
__device__ __forceinline__ ull fma2(ull a, ull b, ull c) {
    ull d;
    asm("fma.rn.f32x2 %0, %1, %2, %3;" : "=l"(d) : "l"(a), "l"(b), "l"(c));
    return d;
}
__device__ __forceinline__ float sum2(ull a) {
    float lo, hi;
    asm("mov.b64 {%0, %1}, %2;" : "=f"(lo), "=f"(hi) : "l"(a));
    return lo + hi;
}

// ---------------- mma.sync m16n8k16 f16 helper ----------------
__device__ __forceinline__ void mma16816(float* d, u32 a0, u32 a1, u32 a2, u32 a3,
                                         u32 b0, u32 b1) {
    asm volatile(
        "mma.sync.aligned.m16n8k16.row.col.f32.f16.f16.f32 "
        "{%0,%1,%2,%3}, {%4,%5,%6,%7}, {%8,%9}, {%0,%1,%2,%3};"
        : "+f"(d[0]), "+f"(d[1]), "+f"(d[2]), "+f"(d[3])
        : "r"(a0), "r"(a1), "r"(a2), "r"(a3), "r"(b0), "r"(b1));
}

__device__ __forceinline__ u32 packh2(float a, float b) {
    __half2 h = __floats2half2_rn(a, b);
    return *(u32*)&h;
}

// ---------------- CSR construction ----------------
__global__ void k_hist(const int* __restrict__ ei) {
    int e = blockIdx.x * blockDim.x + threadIdx.x;
    if (e < N_EDGES) atomicAdd(&g_cnt[ei[N_EDGES + e]], 1);
}

__global__ void k_scan_local() {
    __shared__ int wsums[16];
    int b = blockIdx.x, tid = threadIdx.x, lane = tid & 31, wid = tid >> 5;
    int i = b * 512 + tid;
    int v = (i < N_NODES) ? g_cnt[i] : 0;
    int x = v;
    #pragma unroll
    for (int o = 1; o < 32; o <<= 1) {
        int y = __shfl_up_sync(0xffffffffu, x, o);
        if (lane >= o) x += y;
    }
    if (lane == 31) wsums[wid] = x;
    __syncthreads();
    if (wid == 0 && lane < 16) {
        int w = wsums[lane];
        int xs = w;
        #pragma unroll
        for (int o = 1; o < 16; o <<= 1) {
            int y = __shfl_up_sync(0xffffu, xs, o);
            if (lane >= o) xs += y;
        }
        wsums[lane] = xs - w;
    }
    __syncthreads();
    int excl = x - v + wsums[wid];
    if (i < N_NODES) g_off[i] = excl;
    if (tid == 511) g_bsum[b] = excl + v;
}

__global__ void k_scan_add() {
    __shared__ int part[4];
    int b = blockIdx.x, tid = threadIdx.x, lane = tid & 31, wid = tid >> 5;
    int v = 0;
    if (tid < b) v = g_bsum[tid];      // b <= 97 < 128
    if (tid < 128) {
        #pragma unroll
        for (int o = 16; o > 0; o >>= 1) v += __shfl_xor_sync(0xffffffffu, v, o);
        if (lane == 0) part[wid] = v;
    }
    __syncthreads();
    int add = part[0] + part[1] + part[2] + part[3];
    int i = b * 512 + tid;
    if (i < N_NODES) {
        int o = g_off[i] + add;
        g_off[i] = o;
        g_cur[i] = o;
        g_cnt[i] = 0;   // restore zero-invariant for next replay
    }
    if (i == 0) g_off[N_NODES] = N_EDGES;
}

__global__ void k_scatter(const int* __restrict__ ei) {
    int e = blockIdx.x * blockDim.x + threadIdx.x;
    if (e < N_EDGES) {
        int d = ei[N_EDGES + e];
        int p = atomicAdd(&g_cur[d], 1);
        g_csr[p] = ei[e];
    }
}

// ---------------- weight prep (fake-quant + HMMA fragment layout) ----------------
__global__ void k_quant_prep(const float* __restrict__ W0, const float* __restrict__ Ws,
                             const float* __restrict__ w1, const float* __restrict__ w2,
                             const float* __restrict__ w3) {
    int b = blockIdx.x, tid = threadIdx.x;
    if (b < 5) {
        __shared__ float red[256];
        const float* W = (b == 0) ? W0 : (Ws + (size_t)(b - 1) * 64 * 67);
        int cols = (b == 0) ? 4 : 67;
        int n = 64 * cols;
        float* dst = g_Wq + b * WSZ;

        float m = 0.f;
        for (int i = tid; i < n; i += 256) m = fmaxf(m, fabsf(W[i]));
        red[tid] = m;
        __syncthreads();
        for (int s = 128; s > 0; s >>= 1) {
            if (tid < s) red[tid] = fmaxf(red[tid], red[tid + s]);
            __syncthreads();
        }
        float sc = fmaxf(red[0] * (1.0f / 127.0f), 1e-8f);
        for (int i = tid; i < WSZ; i += 256) dst[i] = 0.0f;
        __syncthreads();
        for (int i = tid; i < n; i += 256) {
            int k = i / cols, c = i % cols;
            float q = rintf(W[i] / sc);
            q = fminf(fmaxf(q, -127.0f), 127.0f) * sc;
            dst[k * WSTRIDE + c] = q;
        }
        return;
    }
    // fragment layout build: 16384 slots (10240 w1, 4096 w2, 2048 w3)
    int idx = (b - 5) * 256 + tid;
    const float* src;
    uint2 *dh, *dl;
    int K, slot;
    if (idx < 10240)      { src = w1; dh = g_w1f_h; dl = g_w1f_l; K = 320; slot = idx;
                            int kt = slot >> 9, rem = slot & 511, nb = rem >> 5, lane = rem & 31;
                            int g = lane >> 2, tq = lane & 3;
                            int n = nb * 8 + g, kb = kt * 16 + tq * 2;
                            float v0 = src[n * K + kb],     v1 = src[n * K + kb + 1];
                            float v2 = src[n * K + kb + 8], v3 = src[n * K + kb + 9];
                            __half h0 = __float2half(v0), h1 = __float2half(v1);
                            __half h2 = __float2half(v2), h3 = __float2half(v3);
                            dh[slot] = make_uint2(packh2(__half2float(h0), __half2float(h1)),
                                                  packh2(__half2float(h2), __half2float(h3)));
                            dl[slot] = make_uint2(packh2(v0 - __half2float(h0), v1 - __half2float(h1)),
                                                  packh2(v2 - __half2float(h2), v3 - __half2float(h3)));
    } else if (idx < 14336) { src = w2; dh = g_w2f_h; dl = g_w2f_l; K = 128; slot = idx - 10240;
                            int kt = slot >> 9, rem = slot & 511, nb = rem >> 5, lane = rem & 31;
                            int g = lane >> 2, tq = lane & 3;
                            int n = nb * 8 + g, kb = kt * 16 + tq * 2;
                            float v0 = src[n * K + kb],     v1 = src[n * K + kb + 1];
                            float v2 = src[n * K + kb + 8], v3 = src[n * K + kb + 9];
                            __half h0 = __float2half(v0), h1 = __float2half(v1);
                            __half h2 = __float2half(v2), h3 = __float2half(v3);
                            dh[slot] = make_uint2(packh2(__half2float(h0), __half2float(h1)),
                                                  packh2(__half2float(h2), __half2float(h3)));
                            dl[slot] = make_uint2(packh2(v0 - __half2float(h0), v1 - __half2float(h1)),
                                                  packh2(v2 - __half2float(h2), v3 - __half2float(h3)));
    } else if (idx < 16384) { src = w3; dh = g_w3f_h; dl = g_w3f_l; K = 128; slot = idx - 14336;
                            int kt = slot >> 8, rem = slot & 255, nb = rem >> 5, lane = rem & 31;
                            int g = lane >> 2, tq = lane & 3;
                            int n = nb * 8 + g, kb = kt * 16 + tq * 2;
                            float v0 = src[n * K + kb],     v1 = src[n * K + kb + 1];
                            float v2 = src[n * K + kb + 8], v3 = src[n * K + kb + 9];
                            __half h0 = __float2half(v0), h1 = __float2half(v1);
                            __half h2 = __float2half(v2), h3 = __float2half(v3);
                            dh[slot] = make_uint2(packh2(__half2float(h0), __half2float(h1)),
                                                  packh2(__half2float(h2), __half2float(h3)));
                            dl[slot] = make_uint2(packh2(v0 - __half2float(h0), v1 - __half2float(h1)),
                                                  packh2(v2 - __half2float(h2), v3 - __half2float(h3)));
    }
}

// ---------------- layer-0 transform ----------------
__global__ __launch_bounds__(256) void k_transform0(const float* __restrict__ x,
                                                    const float* __restrict__ pos) {
    __shared__ float4 Wsh[64];
    __shared__ float  xs[32];
    __shared__ float  ps[96];
    int tid = threadIdx.x;
    int nbase = blockIdx.x * 32;
    if (tid < 64) {
        const float* wr = g_Wq + tid * WSTRIDE;
        Wsh[tid] = make_float4(wr[0], wr[1], wr[2], wr[3]);
    } else if (tid < 96) {
        int n = nbase + (tid - 64);
        xs[tid - 64] = (n < N_NODES) ? x[n] : 0.f;
    } else if (tid < 192) {
        int j = tid - 96;
        int gi = nbase * 3 + j;
        ps[j] = (gi < N_NODES * 3) ? pos[gi] : 0.f;
    }
    __syncthreads();
    int k = tid & 63, grp = tid >> 6;
    float4 w = Wsh[k];
    #pragma unroll
    for (int j = 0; j < 8; j++) {
        int nn = grp * 8 + j;
        int n = nbase + nn;
        if (n < N_NODES) {
            float r = w.x * xs[nn] + w.y * ps[3 * nn] + w.z * ps[3 * nn + 1] + w.w * ps[3 * nn + 2];
            g_uh[(size_t)n * HID + k] = __float2half(r);
        }
    }
}

// ---------------- layers 1-4 transform ----------------
__global__ __launch_bounds__(256) void k_transform(const float* __restrict__ pos, int layer) {
    constexpr int C4 = 17;
    __shared__ float Wsh[WSZ];
    __shared__ float fsh[32][WSTRIDE];
    int tid = threadIdx.x;
    int k = tid & 63, grp = tid >> 6;
    const float* Wsrc = g_Wq + layer * WSZ;
    {
        const float4* s4 = (const float4*)Wsrc;
        float4* d4 = (float4*)Wsh;
        #pragma unroll
        for (int i = tid; i < WSZ / 4; i += 256) d4[i] = s4[i];
    }
    int nbase = blockIdx.x * 32;
    const float* h = g_z + (size_t)(layer - 1) * HID;
    #pragma unroll
    for (int i = tid; i < 32 * 64; i += 256) {
        int nn = i >> 6, c = i & 63;
        int gn = nbase + nn;
        fsh[nn][c] = (gn < N_NODES) ? h[(size_t)gn * ZDIM + c] : 0.f;
    }
    if (tid < 128) {
        int nn = tid >> 2, j = tid & 3;
        int gn = nbase + nn;
        float v = 0.f;
        if (j < 3 && gn < N_NODES) v = pos[gn * 3 + j];
        fsh[nn][64 + j] = v;
    }
    __syncthreads();
    ull w2r[C4 * 2];
    #pragma unroll
    for (int c4 = 0; c4 < C4; c4++) {
        ulonglong2 wv = *(const ulonglong2*)&Wsh[k * WSTRIDE + 4 * c4];
        w2r[2 * c4] = wv.x; w2r[2 * c4 + 1] = wv.y;
    }
    ull acc[8];
    #pragma unroll
    for (int j = 0; j < 8; j++) acc[j] = 0;
    #pragma unroll
    for (int c4 = 0; c4 < C4; c4++) {
        ull w01 = w2r[2 * c4], w23 = w2r[2 * c4 + 1];
        #pragma unroll
        for (int j = 0; j < 8; j++) {
            ulonglong2 f = *(const ulonglong2*)&fsh[grp * 8 + j][4 * c4];
            acc[j] = fma2(f.x, w01, acc[j]);
            acc[j] = fma2(f.y, w23, acc[j]);
        }
    }
    #pragma unroll
    for (int j = 0; j < 8; j++) {
        int n = nbase + grp * 8 + j;
        if (n < N_NODES) g_uh[(size_t)n * HID + k] = __float2half(sum2(acc[j]));
    }
}

// ---------------- aggregation: 2 nodes/warp, 16 lanes x half2x2 (8B/lane) ----------------
__global__ __launch_bounds__(256) void k_aggregate(const float* __restrict__ pos,
                                                   const float* __restrict__ ln_g,
                                                   const float* __restrict__ ln_b,
                                                   int layer, int cols) {
    __shared__ float Wp[64][3];
    __shared__ float gs[64], bs[64];
    int tid = threadIdx.x;
    if (tid < 64) { gs[tid] = ln_g[layer * 64 + tid]; bs[tid] = ln_b[layer * 64 + tid]; }
    const float* Wsrc = g_Wq + layer * WSZ;
    for (int i = tid; i < 192; i += 256) {
        int k = i / 3, j = i % 3;
        Wp[k][j] = Wsrc[k * WSTRIDE + (cols - 3) + j];
    }
    __syncthreads();

    int wid = tid >> 5, lane = tid & 31;
    int half = lane >> 4, l16 = lane & 15;
    int n = blockIdx.x * 16 + wid * 2 + half;
    int s = g_off[n], e = g_off[n + 1];
    const uint2* ubase = (const uint2*)g_uh;

    __half2 M0 = __float2half2_rn(-65504.f);
    __half2 M1 = __float2half2_rn(-65504.f);
    int p = s;
    for (; p + 8 <= e; p += 8) {
        int i0 = g_csr[p],     i1 = g_csr[p + 1], i2 = g_csr[p + 2], i3 = g_csr[p + 3];
        int i4 = g_csr[p + 4], i5 = g_csr[p + 5], i6 = g_csr[p + 6], i7 = g_csr[p + 7];
        uint2 a = __ldcg(&ubase[(size_t)i0 * 16 + l16]);
        uint2 b = __ldcg(&ubase[(size_t)i1 * 16 + l16]);
        uint2 c = __ldcg(&ubase[(size_t)i2 * 16 + l16]);
        uint2 d = __ldcg(&ubase[(size_t)i3 * 16 + l16]);
        uint2 f = __ldcg(&ubase[(size_t)i4 * 16 + l16]);
        uint2 g = __ldcg(&ubase[(size_t)i5 * 16 + l16]);
        uint2 h = __ldcg(&ubase[(size_t)i6 * 16 + l16]);
        uint2 q = __ldcg(&ubase[(size_t)i7 * 16 + l16]);
        M0 = __hmax2(M0, __hmax2(__hmax2(*(__half2*)&a.x, *(__half2*)&b.x),
                                 __hmax2(*(__half2*)&c.x, *(__half2*)&d.x)));
        M0 = __hmax2(M0, __hmax2(__hmax2(*(__half2*)&f.x, *(__half2*)&g.x),
                                 __hmax2(*(__half2*)&h.x, *(__half2*)&q.x)));
        M1 = __hmax2(M1, __hmax2(__hmax2(*(__half2*)&a.y, *(__half2*)&b.y),
                                 __hmax2(*(__half2*)&c.y, *(__half2*)&d.y)));
        M1 = __hmax2(M1, __hmax2(__hmax2(*(__half2*)&f.y, *(__half2*)&g.y),
                                 __hmax2(*(__half2*)&h.y, *(__half2*)&q.y)));
    }
    for (; p + 4 <= e; p += 4) {
        int i0 = g_csr[p], i1 = g_csr[p + 1], i2 = g_csr[p + 2], i3 = g_csr[p + 3];
        uint2 a = __ldcg(&ubase[(size_t)i0 * 16 + l16]);
        uint2 b = __ldcg(&ubase[(size_t)i1 * 16 + l16]);
        uint2 c = __ldcg(&ubase[(size_t)i2 * 16 + l16]);
        uint2 d = __ldcg(&ubase[(size_t)i3 * 16 + l16]);
        M0 = __hmax2(M0, __hmax2(__hmax2(*(__half2*)&a.x, *(__half2*)&b.x),
                                 __hmax2(*(__half2*)&c.x, *(__half2*)&d.x)));
        M1 = __hmax2(M1, __hmax2(__hmax2(*(__half2*)&a.y, *(__half2*)&b.y),
                                 __hmax2(*(__half2*)&c.y, *(__half2*)&d.y)));
    }
    for (; p < e; p++) {
        int i0 = g_csr[p];
        uint2 a = __ldcg(&ubase[(size_t)i0 * 16 + l16]);
        M0 = __hmax2(M0, *(__half2*)&a.x);
        M1 = __hmax2(M1, *(__half2*)&a.y);
    }

    float2 f0 = __half22float2(M0);
    float2 f1 = __half22float2(M1);

    float px = pos[n * 3 + 0], py = pos[n * 3 + 1], pz = pos[n * 3 + 2];
    int k0 = 4 * l16;
    float4 hh = make_float4(0.f, 0.f, 0.f, 0.f);
    if (e > s) {
        hh.x = f0.x - (px * Wp[k0 + 0][0] + py * Wp[k0 + 0][1] + pz * Wp[k0 + 0][2]);
        hh.y = f0.y - (px * Wp[k0 + 1][0] + py * Wp[k0 + 1][1] + pz * Wp[k0 + 1][2]);
        hh.z = f1.x - (px * Wp[k0 + 2][0] + py * Wp[k0 + 2][1] + pz * Wp[k0 + 2][2]);
        hh.w = f1.y - (px * Wp[k0 + 3][0] + py * Wp[k0 + 3][1] + pz * Wp[k0 + 3][2]);
    }

    float sum = hh.x + hh.y + hh.z + hh.w;
    float sq  = hh.x * hh.x + hh.y * hh.y + hh.z * hh.z + hh.w * hh.w;
    #pragma unroll
    for (int o = 8; o > 0; o >>= 1) {
        sum += __shfl_xor_sync(0xffffffffu, sum, o);
        sq  += __shfl_xor_sync(0xffffffffu, sq, o);
    }
    float mean = sum * (1.0f / 64.0f);
    float var  = fmaxf(sq * (1.0f / 64.0f) - mean * mean, 0.f);
    float rstd = rsqrtf(var + 1e-5f);
    float4 o4;
    o4.x = fmaxf((hh.x - mean) * rstd * gs[k0 + 0] + bs[k0 + 0], 0.f);
    o4.y = fmaxf((hh.y - mean) * rstd * gs[k0 + 1] + bs[k0 + 1], 0.f);
    o4.z = fmaxf((hh.z - mean) * rstd * gs[k0 + 2] + bs[k0 + 2], 0.f);
    o4.w = fmaxf((hh.w - mean) * rstd * gs[k0 + 3] + bs[k0 + 3], 0.f);
    *(float4*)&g_z[(size_t)n * ZDIM + layer * 64 + k0] = o4;
}

// ---------------- MLP via HMMA, fragment-ordered weights ----------------
#define OZ32 0              // f32 [16][320]        20480
#define OZH  20480          // half [16][328]       10496
#define OZL  30976          // half [16][328]       10496
#define OH1H 41472          // half [16][136]        4352
#define OH1L 45824
#define OH2H 50176
#define OH2L 54528
#define OH3  58880          // f32 [16][64]          4096
#define OST  62976          // f32 mean[16], rstd[16] 128
#define SMEM_MLP 63104

__global__ __launch_bounds__(128) void k_mlp(const float* __restrict__ b1,
                                             const float* __restrict__ b2,
                                             const float* __restrict__ b3,
                                             const float* __restrict__ w4,
                                             const float* __restrict__ b4,
                                             const float* __restrict__ scale,
                                             float* __restrict__ out) {
    extern __shared__ char sm[];
    float*  zsh = (float*)(sm + OZ32);
    __half* zh  = (__half*)(sm + OZH);
    __half* zl  = (__half*)(sm + OZL);
    __half* h1h = (__half*)(sm + OH1H);
    __half* h1l = (__half*)(sm + OH1L);
    __half* h2h = (__half*)(sm + OH2H);
    __half* h2l = (__half*)(sm + OH2L);
    float*  h3s = (float*)(sm + OH3);
    float*  meansh = (float*)(sm + OST);
    float*  rstdsh = (float*)(sm + OST + 64);

    int tid = threadIdx.x;
    int n0 = blockIdx.x * 16;
    int warp = tid >> 5, lane = tid & 31;
    int g = lane >> 2, tq = lane & 3;

    for (int i = tid; i < 16 * 320; i += 128) zsh[i] = g_z[(size_t)n0 * ZDIM + i];
    __syncthreads();

    // LayerNorm(320), g=1 b=0
    {
        int node = tid >> 3, j = tid & 7;
        float s = 0.f, sq = 0.f;
        for (int c = j; c < 320; c += 8) {
            float v = zsh[node * 320 + c];
            s += v; sq += v * v;
        }
        #pragma unroll
        for (int o = 4; o > 0; o >>= 1) {
            s  += __shfl_down_sync(0xffffffffu, s, o, 8);
            sq += __shfl_down_sync(0xffffffffu, sq, o, 8);
        }
        if (j == 0) {
            float mean = s * (1.0f / 320.0f);
            float var  = fmaxf(sq * (1.0f / 320.0f) - mean * mean, 0.f);
            meansh[node] = mean;
            rstdsh[node] = rsqrtf(var + 1e-5f);
        }
    }
    __syncthreads();
    for (int i = tid; i < 16 * 320; i += 128) {
        int nn = i / 320, c = i - nn * 320;
        float v = (zsh[i] - meansh[nn]) * rstdsh[nn];
        __half h = __float2half(v);
        zh[nn * 328 + c] = h;
        zl[nn * 328 + c] = __float2half(v - __half2float(h));
    }
    __syncthreads();

    float d[4][4];

    // ---- layer 1: 320 -> 128 (4 n-tiles/warp, K=320) ----
    #pragma unroll
    for (int t = 0; t < 4; t++) { d[t][0] = d[t][1] = d[t][2] = d[t][3] = 0.f; }
    #pragma unroll 2
    for (int kt = 0; kt < 20; kt++) {
        int k0 = kt * 16;
        uint2 bh[4], bl[4];
        #pragma unroll
        for (int t = 0; t < 4; t++) {
            int fi = ((kt * 16 + warp * 4 + t) << 5) + lane;
            bh[t] = __ldg(&g_w1f_h[fi]);
            bl[t] = __ldg(&g_w1f_l[fi]);
        }
        u32 ah0 = *(const u32*)&zh[g * 328 + k0 + tq * 2];
        u32 ah1 = *(const u32*)&zh[(g + 8) * 328 + k0 + tq * 2];
        u32 ah2 = *(const u32*)&zh[g * 328 + k0 + 8 + tq * 2];
        u32 ah3 = *(const u32*)&zh[(g + 8) * 328 + k0 + 8 + tq * 2];
        u32 al0 = *(const u32*)&zl[g * 328 + k0 + tq * 2];
        u32 al1 = *(const u32*)&zl[(g + 8) * 328 + k0 + tq * 2];
        u32 al2 = *(const u32*)&zl[g * 328 + k0 + 8 + tq * 2];
        u32 al3 = *(const u32*)&zl[(g + 8) * 328 + k0 + 8 + tq * 2];
        #pragma unroll
        for (int t = 0; t < 4; t++) {
            mma16816(d[t], ah0, ah1, ah2, ah3, bh[t].x, bh[t].y);
            mma16816(d[t], ah0, ah1, ah2, ah3, bl[t].x, bl[t].y);
            mma16816(d[t], al0, al1, al2, al3, bh[t].x, bh[t].y);
        }
    }
    #pragma unroll
    for (int t = 0; t < 4; t++) {
        int col = warp * 32 + t * 8 + tq * 2;
        float bb0 = b1[col], bb1 = b1[col + 1];
        float v00 = fmaxf(d[t][0] + bb0, 0.f), v01 = fmaxf(d[t][1] + bb1, 0.f);
        float v10 = fmaxf(d[t][2] + bb0, 0.f), v11 = fmaxf(d[t][3] + bb1, 0.f);
        __half x;
        x = __float2half(v00); h1h[g * 136 + col] = x; h1l[g * 136 + col] = __float2half(v00 - __half2float(x));
        x = __float2half(v01); h1h[g * 136 + col + 1] = x; h1l[g * 136 + col + 1] = __float2half(v01 - __half2float(x));
        x = __float2half(v10); h1h[(g + 8) * 136 + col] = x; h1l[(g + 8) * 136 + col] = __float2half(v10 - __half2float(x));
        x = __float2half(v11); h1h[(g + 8) * 136 + col + 1] = x; h1l[(g + 8) * 136 + col + 1] = __float2half(v11 - __half2float(x));
    }
    __syncthreads();

    // ---- layer 2: 128 -> 128 ----
    #pragma unroll
    for (int t = 0; t < 4; t++) { d[t][0] = d[t][1] = d[t][2] = d[t][3] = 0.f; }
    #pragma unroll 2
    for (int kt = 0; kt < 8; kt++) {
        int k0 = kt * 16;
        uint2 bh[4], bl[4];
        #pragma unroll
        for (int t = 0; t < 4; t++) {
            int fi = ((kt * 16 + warp * 4 + t) << 5) + lane;
            bh[t] = __ldg(&g_w2f_h[fi]);
            bl[t] = __ldg(&g_w2f_l[fi]);
        }
        u32 ah0 = *(const u32*)&h1h[g * 136 + k0 + tq * 2];
        u32 ah1 = *(const u32*)&h1h[(g + 8) * 136 + k0 + tq * 2];
        u32 ah2 = *(const u32*)&h1h[g * 136 + k0 + 8 + tq * 2];
        u32 ah3 = *(const u32*)&h1h[(g + 8) * 136 + k0 + 8 + tq * 2];
        u32 al0 = *(const u32*)&h1l[g * 136 + k0 + tq * 2];
        u32 al1 = *(const u32*)&h1l[(g + 8) * 136 + k0 + tq * 2];
        u32 al2 = *(const u32*)&h1l[g * 136 + k0 + 8 + tq * 2];
        u32 al3 = *(const u32*)&h1l[(g + 8) * 136 + k0 + 8 + tq * 2];
        #pragma unroll
        for (int t = 0; t < 4; t++) {
            mma16816(d[t], ah0, ah1, ah2, ah3, bh[t].x, bh[t].y);
            mma16816(d[t], ah0, ah1, ah2, ah3, bl[t].x, bl[t].y);
            mma16816(d[t], al0, al1, al2, al3, bh[t].x, bh[t].y);
        }
    }
    #pragma unroll
    for (int t = 0; t < 4; t++) {
        int col = warp * 32 + t * 8 + tq * 2;
        float bb0 = b2[col], bb1 = b2[col + 1];
        float v00 = fmaxf(d[t][0] + bb0, 0.f), v01 = fmaxf(d[t][1] + bb1, 0.f);
        float v10 = fmaxf(d[t][2] + bb0, 0.f), v11 = fmaxf(d[t][3] + bb1, 0.f);
        __half x;
        x = __float2half(v00); h2h[g * 136 + col] = x; h2l[g * 136 + col] = __float2half(v00 - __half2float(x));
        x = __float2half(v01); h2h[g * 136 + col + 1] = x; h2l[g * 136 + col + 1] = __float2half(v01 - __half2float(x));
        x = __float2half(v10); h2h[(g + 8) * 136 + col] = x; h2l[(g + 8) * 136 + col] = __float2half(v10 - __half2float(x));
        x = __float2half(v11); h2h[(g + 8) * 136 + col + 1] = x; h2l[(g + 8) * 136 + col + 1] = __float2half(v11 - __half2float(x));
    }
    __syncthreads();

    // ---- layer 3: 128 -> 64 (2 n-tiles/warp) ----
    #pragma unroll
    for (int t = 0; t < 2; t++) { d[t][0] = d[t][1] = d[t][2] = d[t][3] = 0.f; }
    #pragma unroll 2
    for (int kt = 0; kt < 8; kt++) {
        int k0 = kt * 16;
        uint2 bh[2], bl[2];
        #pragma unroll
        for (int t = 0; t < 2; t++) {
            int fi = ((kt * 8 + warp * 2 + t) << 5) + lane;
            bh[t] = __ldg(&g_w3f_h[fi]);
            bl[t] = __ldg(&g_w3f_l[fi]);
        }
        u32 ah0 = *(const u32*)&h2h[g * 136 + k0 + tq * 2];
        u32 ah1 = *(const u32*)&h2h[(g + 8) * 136 + k0 + tq * 2];
        u32 ah2 = *(const u32*)&h2h[g * 136 + k0 + 8 + tq * 2];
        u32 ah3 = *(const u32*)&h2h[(g + 8) * 136 + k0 + 8 + tq * 2];
        u32 al0 = *(const u32*)&h2l[g * 136 + k0 + tq * 2];
        u32 al1 = *(const u32*)&h2l[(g + 8) * 136 + k0 + tq * 2];
        u32 al2 = *(const u32*)&h2l[g * 136 + k0 + 8 + tq * 2];
        u32 al3 = *(const u32*)&h2l[(g + 8) * 136 + k0 + 8 + tq * 2];
        #pragma unroll
        for (int t = 0; t < 2; t++) {
            mma16816(d[t], ah0, ah1, ah2, ah3, bh[t].x, bh[t].y);
            mma16816(d[t], ah0, ah1, ah2, ah3, bl[t].x, bl[t].y);
            mma16816(d[t], al0, al1, al2, al3, bh[t].x, bh[t].y);
        }
    }
    #pragma unroll
    for (int t = 0; t < 2; t++) {
        int col = warp * 16 + t * 8 + tq * 2;
        float bb0 = b3[col], bb1 = b3[col + 1];
        h3s[g * 64 + col]           = fmaxf(d[t][0] + bb0, 0.f);
        h3s[g * 64 + col + 1]       = fmaxf(d[t][1] + bb1, 0.f);
        h3s[(g + 8) * 64 + col]     = fmaxf(d[t][2] + bb0, 0.f);
        h3s[(g + 8) * 64 + col + 1] = fmaxf(d[t][3] + bb1, 0.f);
    }
    __syncthreads();

    // ---- layer 4: 64 -> 2, * scale ----
    if (tid < 32) {
        int nn = tid >> 1, o = tid & 1;
        float a = b4[o];
        const float* wrow = &w4[o * 64];
        #pragma unroll 8
        for (int c = 0; c < 64; c++) a += h3s[nn * 64 + c] * wrow[c];
        out[(size_t)(n0 + nn) * 2 + o] = a * scale[o];
    }
}

// ---------------- launch ----------------
extern "C" void kernel_launch(void* const* d_in, const int* in_sizes, int n_in,
                              void* d_out, int out_size) {
    const float* x     = (const float*)d_in[0];
    const float* pos   = (const float*)d_in[1];
    const int*   ei    = (const int*)d_in[2];
    const float* W0    = (const float*)d_in[3];
    const float* Ws    = (const float*)d_in[4];
    const float* ln_g  = (const float*)d_in[5];
    const float* ln_b  = (const float*)d_in[6];
    const float* w1    = (const float*)d_in[7];
    const float* b1    = (const float*)d_in[8];
    const float* w2    = (const float*)d_in[9];
    const float* b2    = (const float*)d_in[10];
    const float* w3    = (const float*)d_in[11];
    const float* b3    = (const float*)d_in[12];
    const float* w4    = (const float*)d_in[13];
    const float* b4    = (const float*)d_in[14];
    const float* scale = (const float*)d_in[15];
    float* out = (float*)d_out;

    cudaFuncSetAttribute(k_mlp, cudaFuncAttributeMaxDynamicSharedMemorySize, SMEM_MLP);

    const int TGRID = (N_NODES + 31) / 32;  // 1563

    k_hist<<<(N_EDGES + 255) / 256, 256>>>(ei);                    // #1
    k_quant_prep<<<69, 256>>>(W0, Ws, w1, w2, w3);                 // #2
    k_scan_local<<<SCAN_BLK, 512>>>();                             // #3
    k_transform0<<<TGRID, 256>>>(x, pos);                          // #4  <- profiled
    k_scan_add<<<SCAN_BLK, 512>>>();                               // #5
    k_scatter<<<(N_EDGES + 255) / 256, 256>>>(ei);                 // #6
    k_aggregate<<<N_NODES / 16, 256>>>(pos, ln_g, ln_b, 0, 4);     // #7

    for (int i = 1; i < 5; i++) {
        k_transform<<<TGRID, 256>>>(pos, i);
        k_aggregate<<<N_NODES / 16, 256>>>(pos, ln_g, ln_b, i, 67);
    }

    k_mlp<<<N_NODES / 16, 128, SMEM_MLP>>>(b1, b2, b3, w4, b4, scale, out);
}

// round 14
// speedup vs baseline: 1.2608x; 1.1631x over previous
#include <cuda_runtime.h>
#include <cuda_bf16.h>
#include <cuda_fp16.h>
#include <cfloat>
#include <cstdint>

#define N_NODES 50000
#define N_EDGES 800000
#define HID 64
#define ZDIM 320
#define WSTRIDE 68                 // padded W row (64x68, zeros in pad)
#define WSZ (64 * WSTRIDE)
#define SCAN_BLK 98                // ceil(50000/512)
#define NPADZ 50016                // pad g_z rows for 32-node MLP tiles

typedef unsigned long long ull;
typedef uint32_t u32;

// ---------------- device scratch ----------------
__device__ __half g_uh[N_NODES * HID];     // u stored fp16 (gather payload)
__device__ float g_z[NPADZ * ZDIM];        // pad rows never written -> zero
__device__ int   g_cnt[N_NODES];           // INVARIANT: all-zero at kernel_launch entry
__device__ int   g_off[N_NODES + 1];
__device__ int   g_cur[N_NODES];
__device__ int   g_csr[N_EDGES];
__device__ int   g_bsum[SCAN_BLK];
__device__ float g_Wq[5 * WSZ];            // all 5 quantized layer weights
// HMMA fragment-ordered weights (hi/lo fp16 split):
__device__ uint2 g_w1f_h[20 * 16 * 32], g_w1f_l[20 * 16 * 32];   // 320->128
__device__ uint2 g_w2f_h[8 * 16 * 32],  g_w2f_l[8 * 16 * 32];    // 128->128
__device__ uint2 g_w3f_h[8 * 8 * 32],   g_w3f_l[8 * 8 * 32];     // 128->64

// ---------------- f32x2 helpers ----------------
__device__ __forceinline__ ull fma2(ull a, ull b, ull c) {
    ull d;
    asm("fma.rn.f32x2 %0, %1, %2, %3;" : "=l"(d) : "l"(a), "l"(b), "l"(c));
    return d;
}
__device__ __forceinline__ float sum2(ull a) {
    float lo, hi;
    asm("mov.b64 {%0, %1}, %2;" : "=f"(lo), "=f"(hi) : "l"(a));
    return lo + hi;
}

// ---------------- mma.sync m16n8k16 f16 helper ----------------
__device__ __forceinline__ void mma16816(float* d, u32 a0, u32 a1, u32 a2, u32 a3,
                                         u32 b0, u32 b1) {
    asm volatile(
        "mma.sync.aligned.m16n8k16.row.col.f32.f16.f16.f32 "
        "{%0,%1,%2,%3}, {%4,%5,%6,%7}, {%8,%9}, {%0,%1,%2,%3};"
        : "+f"(d[0]), "+f"(d[1]), "+f"(d[2]), "+f"(d[3])
        : "r"(a0), "r"(a1), "r"(a2), "r"(a3), "r"(b0), "r"(b1));
}

__device__ __forceinline__ u32 packh2(float a, float b) {
    __half2 h = __floats2half2_rn(a, b);
    return *(u32*)&h;
}

// ---------------- CSR construction ----------------
__global__ void k_hist(const int* __restrict__ ei) {
    int e = blockIdx.x * blockDim.x + threadIdx.x;
    if (e < N_EDGES) atomicAdd(&g_cnt[ei[N_EDGES + e]], 1);
}

__global__ void k_scan_local() {
    __shared__ int wsums[16];
    int b = blockIdx.x, tid = threadIdx.x, lane = tid & 31, wid = tid >> 5;
    int i = b * 512 + tid;
    int v = (i < N_NODES) ? g_cnt[i] : 0;
    int x = v;
    #pragma unroll
    for (int o = 1; o < 32; o <<= 1) {
        int y = __shfl_up_sync(0xffffffffu, x, o);
        if (lane >= o) x += y;
    }
    if (lane == 31) wsums[wid] = x;
    __syncthreads();
    if (wid == 0 && lane < 16) {
        int w = wsums[lane];
        int xs = w;
        #pragma unroll
        for (int o = 1; o < 16; o <<= 1) {
            int y = __shfl_up_sync(0xffffu, xs, o);
            if (lane >= o) xs += y;
        }
        wsums[lane] = xs - w;
    }
    __syncthreads();
    int excl = x - v + wsums[wid];
    if (i < N_NODES) g_off[i] = excl;
    if (tid == 511) g_bsum[b] = excl + v;
}

__global__ void k_scan_add() {
    __shared__ int part[4];
    int b = blockIdx.x, tid = threadIdx.x, lane = tid & 31, wid = tid >> 5;
    int v = 0;
    if (tid < b) v = g_bsum[tid];      // b <= 97 < 128
    if (tid < 128) {
        #pragma unroll
        for (int o = 16; o > 0; o >>= 1) v += __shfl_xor_sync(0xffffffffu, v, o);
        if (lane == 0) part[wid] = v;
    }
    __syncthreads();
    int add = part[0] + part[1] + part[2] + part[3];
    int i = b * 512 + tid;
    if (i < N_NODES) {
        int o = g_off[i] + add;
        g_off[i] = o;
        g_cur[i] = o;
        g_cnt[i] = 0;   // restore zero-invariant for next replay
    }
    if (i == 0) g_off[N_NODES] = N_EDGES;
}

__global__ void k_scatter(const int* __restrict__ ei) {
    int e = blockIdx.x * blockDim.x + threadIdx.x;
    if (e < N_EDGES) {
        int d = ei[N_EDGES + e];
        int p = atomicAdd(&g_cur[d], 1);
        g_csr[p] = ei[e];
    }
}

// ---------------- weight prep (fake-quant + HMMA fragment layout) ----------------
__global__ void k_quant_prep(const float* __restrict__ W0, const float* __restrict__ Ws,
                             const float* __restrict__ w1, const float* __restrict__ w2,
                             const float* __restrict__ w3) {
    int b = blockIdx.x, tid = threadIdx.x;
    if (b < 5) {
        __shared__ float red[256];
        const float* W = (b == 0) ? W0 : (Ws + (size_t)(b - 1) * 64 * 67);
        int cols = (b == 0) ? 4 : 67;
        int n = 64 * cols;
        float* dst = g_Wq + b * WSZ;

        float m = 0.f;
        for (int i = tid; i < n; i += 256) m = fmaxf(m, fabsf(W[i]));
        red[tid] = m;
        __syncthreads();
        for (int s = 128; s > 0; s >>= 1) {
            if (tid < s) red[tid] = fmaxf(red[tid], red[tid + s]);
            __syncthreads();
        }
        float sc = fmaxf(red[0] * (1.0f / 127.0f), 1e-8f);
        for (int i = tid; i < WSZ; i += 256) dst[i] = 0.0f;
        __syncthreads();
        for (int i = tid; i < n; i += 256) {
            int k = i / cols, c = i % cols;
            float q = rintf(W[i] / sc);
            q = fminf(fmaxf(q, -127.0f), 127.0f) * sc;
            dst[k * WSTRIDE + c] = q;
        }
        return;
    }
    int idx = (b - 5) * 256 + tid;
    const float* src;
    uint2 *dh, *dl;
    int K, slot;
    if (idx < 10240)      { src = w1; dh = g_w1f_h; dl = g_w1f_l; K = 320; slot = idx;
                            int kt = slot >> 9, rem = slot & 511, nb = rem >> 5, lane = rem & 31;
                            int g = lane >> 2, tq = lane & 3;
                            int n = nb * 8 + g, kb = kt * 16 + tq * 2;
                            float v0 = src[n * K + kb],     v1 = src[n * K + kb + 1];
                            float v2 = src[n * K + kb + 8], v3 = src[n * K + kb + 9];
                            __half h0 = __float2half(v0), h1 = __float2half(v1);
                            __half h2 = __float2half(v2), h3 = __float2half(v3);
                            dh[slot] = make_uint2(packh2(__half2float(h0), __half2float(h1)),
                                                  packh2(__half2float(h2), __half2float(h3)));
                            dl[slot] = make_uint2(packh2(v0 - __half2float(h0), v1 - __half2float(h1)),
                                                  packh2(v2 - __half2float(h2), v3 - __half2float(h3)));
    } else if (idx < 14336) { src = w2; dh = g_w2f_h; dl = g_w2f_l; K = 128; slot = idx - 10240;
                            int kt = slot >> 9, rem = slot & 511, nb = rem >> 5, lane = rem & 31;
                            int g = lane >> 2, tq = lane & 3;
                            int n = nb * 8 + g, kb = kt * 16 + tq * 2;
                            float v0 = src[n * K + kb],     v1 = src[n * K + kb + 1];
                            float v2 = src[n * K + kb + 8], v3 = src[n * K + kb + 9];
                            __half h0 = __float2half(v0), h1 = __float2half(v1);
                            __half h2 = __float2half(v2), h3 = __float2half(v3);
                            dh[slot] = make_uint2(packh2(__half2float(h0), __half2float(h1)),
                                                  packh2(__half2float(h2), __half2float(h3)));
                            dl[slot] = make_uint2(packh2(v0 - __half2float(h0), v1 - __half2float(h1)),
                                                  packh2(v2 - __half2float(h2), v3 - __half2float(h3)));
    } else if (idx < 16384) { src = w3; dh = g_w3f_h; dl = g_w3f_l; K = 128; slot = idx - 14336;
                            int kt = slot >> 8, rem = slot & 255, nb = rem >> 5, lane = rem & 31;
                            int g = lane >> 2, tq = lane & 3;
                            int n = nb * 8 + g, kb = kt * 16 + tq * 2;
                            float v0 = src[n * K + kb],     v1 = src[n * K + kb + 1];
                            float v2 = src[n * K + kb + 8], v3 = src[n * K + kb + 9];
                            __half h0 = __float2half(v0), h1 = __float2half(v1);
                            __half h2 = __float2half(v2), h3 = __float2half(v3);
                            dh[slot] = make_uint2(packh2(__half2float(h0), __half2float(h1)),
                                                  packh2(__half2float(h2), __half2float(h3)));
                            dl[slot] = make_uint2(packh2(v0 - __half2float(h0), v1 - __half2float(h1)),
                                                  packh2(v2 - __half2float(h2), v3 - __half2float(h3)));
    }
}

// ---------------- layer-0 transform ----------------
__global__ __launch_bounds__(256) void k_transform0(const float* __restrict__ x,
                                                    const float* __restrict__ pos) {
    __shared__ float4 Wsh[64];
    __shared__ float  xs[32];
    __shared__ float  ps[96];
    int tid = threadIdx.x;
    int nbase = blockIdx.x * 32;
    if (tid < 64) {
        const float* wr = g_Wq + tid * WSTRIDE;
        Wsh[tid] = make_float4(wr[0], wr[1], wr[2], wr[3]);
    } else if (tid < 96) {
        int n = nbase + (tid - 64);
        xs[tid - 64] = (n < N_NODES) ? x[n] : 0.f;
    } else if (tid < 192) {
        int j = tid - 96;
        int gi = nbase * 3 + j;
        ps[j] = (gi < N_NODES * 3) ? pos[gi] : 0.f;
    }
    __syncthreads();
    int k = tid & 63, grp = tid >> 6;
    float4 w = Wsh[k];
    #pragma unroll
    for (int j = 0; j < 8; j++) {
        int nn = grp * 8 + j;
        int n = nbase + nn;
        if (n < N_NODES) {
            float r = w.x * xs[nn] + w.y * ps[3 * nn] + w.z * ps[3 * nn + 1] + w.w * ps[3 * nn + 2];
            g_uh[(size_t)n * HID + k] = __float2half(r);
        }
    }
}

// ---------------- layers 1-4 transform ----------------
__global__ __launch_bounds__(256) void k_transform(const float* __restrict__ pos, int layer) {
    constexpr int C4 = 17;
    __shared__ float Wsh[WSZ];
    __shared__ float fsh[32][WSTRIDE];
    int tid = threadIdx.x;
    int k = tid & 63, grp = tid >> 6;
    const float* Wsrc = g_Wq + layer * WSZ;
    {
        const float4* s4 = (const float4*)Wsrc;
        float4* d4 = (float4*)Wsh;
        #pragma unroll
        for (int i = tid; i < WSZ / 4; i += 256) d4[i] = s4[i];
    }
    int nbase = blockIdx.x * 32;
    const float* h = g_z + (size_t)(layer - 1) * HID;
    #pragma unroll
    for (int i = tid; i < 32 * 64; i += 256) {
        int nn = i >> 6, c = i & 63;
        int gn = nbase + nn;
        fsh[nn][c] = (gn < N_NODES) ? h[(size_t)gn * ZDIM + c] : 0.f;
    }
    if (tid < 128) {
        int nn = tid >> 2, j = tid & 3;
        int gn = nbase + nn;
        float v = 0.f;
        if (j < 3 && gn < N_NODES) v = pos[gn * 3 + j];
        fsh[nn][64 + j] = v;
    }
    __syncthreads();
    ull w2r[C4 * 2];
    #pragma unroll
    for (int c4 = 0; c4 < C4; c4++) {
        ulonglong2 wv = *(const ulonglong2*)&Wsh[k * WSTRIDE + 4 * c4];
        w2r[2 * c4] = wv.x; w2r[2 * c4 + 1] = wv.y;
    }
    ull acc[8];
    #pragma unroll
    for (int j = 0; j < 8; j++) acc[j] = 0;
    #pragma unroll
    for (int c4 = 0; c4 < C4; c4++) {
        ull w01 = w2r[2 * c4], w23 = w2r[2 * c4 + 1];
        #pragma unroll
        for (int j = 0; j < 8; j++) {
            ulonglong2 f = *(const ulonglong2*)&fsh[grp * 8 + j][4 * c4];
            acc[j] = fma2(f.x, w01, acc[j]);
            acc[j] = fma2(f.y, w23, acc[j]);
        }
    }
    #pragma unroll
    for (int j = 0; j < 8; j++) {
        int n = nbase + grp * 8 + j;
        if (n < N_NODES) g_uh[(size_t)n * HID + k] = __float2half(sum2(acc[j]));
    }
}

// ---------------- aggregation: 2 nodes/warp, 16 lanes x half2x2 (8B/lane) ----------------
__global__ __launch_bounds__(256) void k_aggregate(const float* __restrict__ pos,
                                                   const float* __restrict__ ln_g,
                                                   const float* __restrict__ ln_b,
                                                   int layer, int cols) {
    __shared__ float Wp[64][3];
    __shared__ float gs[64], bs[64];
    int tid = threadIdx.x;
    if (tid < 64) { gs[tid] = ln_g[layer * 64 + tid]; bs[tid] = ln_b[layer * 64 + tid]; }
    const float* Wsrc = g_Wq + layer * WSZ;
    for (int i = tid; i < 192; i += 256) {
        int k = i / 3, j = i % 3;
        Wp[k][j] = Wsrc[k * WSTRIDE + (cols - 3) + j];
    }
    __syncthreads();

    int wid = tid >> 5, lane = tid & 31;
    int half = lane >> 4, l16 = lane & 15;
    int n = blockIdx.x * 16 + wid * 2 + half;
    int s = g_off[n], e = g_off[n + 1];
    const uint2* ubase = (const uint2*)g_uh;

    __half2 M0 = __float2half2_rn(-65504.f);
    __half2 M1 = __float2half2_rn(-65504.f);
    int p = s;
    for (; p + 8 <= e; p += 8) {
        int i0 = g_csr[p],     i1 = g_csr[p + 1], i2 = g_csr[p + 2], i3 = g_csr[p + 3];
        int i4 = g_csr[p + 4], i5 = g_csr[p + 5], i6 = g_csr[p + 6], i7 = g_csr[p + 7];
        uint2 a = __ldcg(&ubase[(size_t)i0 * 16 + l16]);
        uint2 b = __ldcg(&ubase[(size_t)i1 * 16 + l16]);
        uint2 c = __ldcg(&ubase[(size_t)i2 * 16 + l16]);
        uint2 d = __ldcg(&ubase[(size_t)i3 * 16 + l16]);
        uint2 f = __ldcg(&ubase[(size_t)i4 * 16 + l16]);
        uint2 g = __ldcg(&ubase[(size_t)i5 * 16 + l16]);
        uint2 h = __ldcg(&ubase[(size_t)i6 * 16 + l16]);
        uint2 q = __ldcg(&ubase[(size_t)i7 * 16 + l16]);
        M0 = __hmax2(M0, __hmax2(__hmax2(*(__half2*)&a.x, *(__half2*)&b.x),
                                 __hmax2(*(__half2*)&c.x, *(__half2*)&d.x)));
        M0 = __hmax2(M0, __hmax2(__hmax2(*(__half2*)&f.x, *(__half2*)&g.x),
                                 __hmax2(*(__half2*)&h.x, *(__half2*)&q.x)));
        M1 = __hmax2(M1, __hmax2(__hmax2(*(__half2*)&a.y, *(__half2*)&b.y),
                                 __hmax2(*(__half2*)&c.y, *(__half2*)&d.y)));
        M1 = __hmax2(M1, __hmax2(__hmax2(*(__half2*)&f.y, *(__half2*)&g.y),
                                 __hmax2(*(__half2*)&h.y, *(__half2*)&q.y)));
    }
    for (; p + 4 <= e; p += 4) {
        int i0 = g_csr[p], i1 = g_csr[p + 1], i2 = g_csr[p + 2], i3 = g_csr[p + 3];
        uint2 a = __ldcg(&ubase[(size_t)i0 * 16 + l16]);
        uint2 b = __ldcg(&ubase[(size_t)i1 * 16 + l16]);
        uint2 c = __ldcg(&ubase[(size_t)i2 * 16 + l16]);
        uint2 d = __ldcg(&ubase[(size_t)i3 * 16 + l16]);
        M0 = __hmax2(M0, __hmax2(__hmax2(*(__half2*)&a.x, *(__half2*)&b.x),
                                 __hmax2(*(__half2*)&c.x, *(__half2*)&d.x)));
        M1 = __hmax2(M1, __hmax2(__hmax2(*(__half2*)&a.y, *(__half2*)&b.y),
                                 __hmax2(*(__half2*)&c.y, *(__half2*)&d.y)));
    }
    for (; p < e; p++) {
        int i0 = g_csr[p];
        uint2 a = __ldcg(&ubase[(size_t)i0 * 16 + l16]);
        M0 = __hmax2(M0, *(__half2*)&a.x);
        M1 = __hmax2(M1, *(__half2*)&a.y);
    }

    float2 f0 = __half22float2(M0);
    float2 f1 = __half22float2(M1);

    float px = pos[n * 3 + 0], py = pos[n * 3 + 1], pz = pos[n * 3 + 2];
    int k0 = 4 * l16;
    float4 hh = make_float4(0.f, 0.f, 0.f, 0.f);
    if (e > s) {
        hh.x = f0.x - (px * Wp[k0 + 0][0] + py * Wp[k0 + 0][1] + pz * Wp[k0 + 0][2]);
        hh.y = f0.y - (px * Wp[k0 + 1][0] + py * Wp[k0 + 1][1] + pz * Wp[k0 + 1][2]);
        hh.z = f1.x - (px * Wp[k0 + 2][0] + py * Wp[k0 + 2][1] + pz * Wp[k0 + 2][2]);
        hh.w = f1.y - (px * Wp[k0 + 3][0] + py * Wp[k0 + 3][1] + pz * Wp[k0 + 3][2]);
    }

    float sum = hh.x + hh.y + hh.z + hh.w;
    float sq  = hh.x * hh.x + hh.y * hh.y + hh.z * hh.z + hh.w * hh.w;
    #pragma unroll
    for (int o = 8; o > 0; o >>= 1) {
        sum += __shfl_xor_sync(0xffffffffu, sum, o);
        sq  += __shfl_xor_sync(0xffffffffu, sq, o);
    }
    float mean = sum * (1.0f / 64.0f);
    float var  = fmaxf(sq * (1.0f / 64.0f) - mean * mean, 0.f);
    float rstd = rsqrtf(var + 1e-5f);
    float4 o4;
    o4.x = fmaxf((hh.x - mean) * rstd * gs[k0 + 0] + bs[k0 + 0], 0.f);
    o4.y = fmaxf((hh.y - mean) * rstd * gs[k0 + 1] + bs[k0 + 1], 0.f);
    o4.z = fmaxf((hh.z - mean) * rstd * gs[k0 + 2] + bs[k0 + 2], 0.f);
    o4.w = fmaxf((hh.w - mean) * rstd * gs[k0 + 3] + bs[k0 + 3], 0.f);
    *(float4*)&g_z[(size_t)n * ZDIM + layer * 64 + k0] = o4;
}

// ---------------- MLP via HMMA, 32-node tile, fragment-ordered weights ----------------
// smem (bytes): zh[32][328] 20992 | zl 20992 | h1h[32][136] 8704 | h1l 8704 |
//               h2h 8704 | h2l 8704 | h3[32][64]f32 8192 | stats 256
#define OZH  0
#define OZL  20992
#define OH1H 41984
#define OH1L 50688
#define OH2H 59392
#define OH2L 68096
#define OH3  76800
#define OST  84992
#define SMEM_MLP 85248

__global__ __launch_bounds__(128) void k_mlp(const float* __restrict__ b1,
                                             const float* __restrict__ b2,
                                             const float* __restrict__ b3,
                                             const float* __restrict__ w4,
                                             const float* __restrict__ b4,
                                             const float* __restrict__ scale,
                                             float* __restrict__ out) {
    extern __shared__ char sm[];
    __half* zh  = (__half*)(sm + OZH);
    __half* zl  = (__half*)(sm + OZL);
    __half* h1h = (__half*)(sm + OH1H);
    __half* h1l = (__half*)(sm + OH1L);
    __half* h2h = (__half*)(sm + OH2H);
    __half* h2l = (__half*)(sm + OH2L);
    float*  h3s = (float*)(sm + OH3);
    float*  meansh = (float*)(sm + OST);
    float*  rstdsh = (float*)(sm + OST + 128);

    int tid = threadIdx.x;
    int n0 = blockIdx.x * 32;            // last block: 16 real + 16 pad (zero) rows
    int warp = tid >> 5, lane = tid & 31;
    int g = lane >> 2, tq = lane & 3;

    // LN stats straight from g_z (pad rows are zero)
    {
        int node = warp * 8 + (lane >> 2), j = lane & 3;
        const float4* zr = (const float4*)&g_z[(size_t)(n0 + node) * ZDIM];
        float s = 0.f, sq = 0.f;
        for (int i = j; i < 80; i += 4) {
            float4 v = zr[i];
            s += v.x + v.y + v.z + v.w;
            sq += v.x * v.x + v.y * v.y + v.z * v.z + v.w * v.w;
        }
        s  += __shfl_down_sync(0xffffffffu, s, 2, 4);
        s  += __shfl_down_sync(0xffffffffu, s, 1, 4);
        sq += __shfl_down_sync(0xffffffffu, sq, 2, 4);
        sq += __shfl_down_sync(0xffffffffu, sq, 1, 4);
        if (j == 0) {
            float mean = s * (1.0f / 320.0f);
            float var  = fmaxf(sq * (1.0f / 320.0f) - mean * mean, 0.f);
            meansh[node] = mean;
            rstdsh[node] = rsqrtf(var + 1e-5f);
        }
    }
    __syncthreads();
    // normalize + fp16 hi/lo split into smem
    for (int i = tid; i < 32 * 320; i += 128) {
        int nn = i / 320, c = i - nn * 320;
        float v = (g_z[(size_t)(n0 + nn) * ZDIM + c] - meansh[nn]) * rstdsh[nn];
        __half h = __float2half(v);
        zh[nn * 328 + c] = h;
        zl[nn * 328 + c] = __float2half(v - __half2float(h));
    }
    __syncthreads();

    float d[2][4][4];

    // ---- layer 1: 320 -> 128 (2 m-tiles x 4 n-tiles/warp, K=320) ----
    #pragma unroll
    for (int m = 0; m < 2; m++)
        #pragma unroll
        for (int t = 0; t < 4; t++) { d[m][t][0] = d[m][t][1] = d[m][t][2] = d[m][t][3] = 0.f; }
    for (int kt = 0; kt < 20; kt++) {
        int k0 = kt * 16;
        uint2 bh[4], bl[4];
        #pragma unroll
        for (int t = 0; t < 4; t++) {
            int fi = ((kt * 16 + warp * 4 + t) << 5) + lane;
            bh[t] = __ldg(&g_w1f_h[fi]);
            bl[t] = __ldg(&g_w1f_l[fi]);
        }
        #pragma unroll
        for (int m = 0; m < 2; m++) {
            int r0 = m * 16 + g, r1 = m * 16 + 8 + g;
            u32 ah0 = *(const u32*)&zh[r0 * 328 + k0 + tq * 2];
            u32 ah1 = *(const u32*)&zh[r1 * 328 + k0 + tq * 2];
            u32 ah2 = *(const u32*)&zh[r0 * 328 + k0 + 8 + tq * 2];
            u32 ah3 = *(const u32*)&zh[r1 * 328 + k0 + 8 + tq * 2];
            u32 al0 = *(const u32*)&zl[r0 * 328 + k0 + tq * 2];
            u32 al1 = *(const u32*)&zl[r1 * 328 + k0 + tq * 2];
            u32 al2 = *(const u32*)&zl[r0 * 328 + k0 + 8 + tq * 2];
            u32 al3 = *(const u32*)&zl[r1 * 328 + k0 + 8 + tq * 2];
            #pragma unroll
            for (int t = 0; t < 4; t++) {
                mma16816(d[m][t], ah0, ah1, ah2, ah3, bh[t].x, bh[t].y);
                mma16816(d[m][t], ah0, ah1, ah2, ah3, bl[t].x, bl[t].y);
                mma16816(d[m][t], al0, al1, al2, al3, bh[t].x, bh[t].y);
            }
        }
    }
    #pragma unroll
    for (int m = 0; m < 2; m++)
        #pragma unroll
        for (int t = 0; t < 4; t++) {
            int col = warp * 32 + t * 8 + tq * 2;
            float bb0 = b1[col], bb1 = b1[col + 1];
            int r0 = m * 16 + g, r1 = m * 16 + 8 + g;
            float v00 = fmaxf(d[m][t][0] + bb0, 0.f), v01 = fmaxf(d[m][t][1] + bb1, 0.f);
            float v10 = fmaxf(d[m][t][2] + bb0, 0.f), v11 = fmaxf(d[m][t][3] + bb1, 0.f);
            __half x;
            x = __float2half(v00); h1h[r0 * 136 + col] = x; h1l[r0 * 136 + col] = __float2half(v00 - __half2float(x));
            x = __float2half(v01); h1h[r0 * 136 + col + 1] = x; h1l[r0 * 136 + col + 1] = __float2half(v01 - __half2float(x));
            x = __float2half(v10); h1h[r1 * 136 + col] = x; h1l[r1 * 136 + col] = __float2half(v10 - __half2float(x));
            x = __float2half(v11); h1h[r1 * 136 + col + 1] = x; h1l[r1 * 136 + col + 1] = __float2half(v11 - __half2float(x));
        }
    __syncthreads();

    // ---- layer 2: 128 -> 128 ----
    #pragma unroll
    for (int m = 0; m < 2; m++)
        #pragma unroll
        for (int t = 0; t < 4; t++) { d[m][t][0] = d[m][t][1] = d[m][t][2] = d[m][t][3] = 0.f; }
    for (int kt = 0; kt < 8; kt++) {
        int k0 = kt * 16;
        uint2 bh[4], bl[4];
        #pragma unroll
        for (int t = 0; t < 4; t++) {
            int fi = ((kt * 16 + warp * 4 + t) << 5) + lane;
            bh[t] = __ldg(&g_w2f_h[fi]);
            bl[t] = __ldg(&g_w2f_l[fi]);
        }
        #pragma unroll
        for (int m = 0; m < 2; m++) {
            int r0 = m * 16 + g, r1 = m * 16 + 8 + g;
            u32 ah0 = *(const u32*)&h1h[r0 * 136 + k0 + tq * 2];
            u32 ah1 = *(const u32*)&h1h[r1 * 136 + k0 + tq * 2];
            u32 ah2 = *(const u32*)&h1h[r0 * 136 + k0 + 8 + tq * 2];
            u32 ah3 = *(const u32*)&h1h[r1 * 136 + k0 + 8 + tq * 2];
            u32 al0 = *(const u32*)&h1l[r0 * 136 + k0 + tq * 2];
            u32 al1 = *(const u32*)&h1l[r1 * 136 + k0 + tq * 2];
            u32 al2 = *(const u32*)&h1l[r0 * 136 + k0 + 8 + tq * 2];
            u32 al3 = *(const u32*)&h1l[r1 * 136 + k0 + 8 + tq * 2];
            #pragma unroll
            for (int t = 0; t < 4; t++) {
                mma16816(d[m][t], ah0, ah1, ah2, ah3, bh[t].x, bh[t].y);
                mma16816(d[m][t], ah0, ah1, ah2, ah3, bl[t].x, bl[t].y);
                mma16816(d[m][t], al0, al1, al2, al3, bh[t].x, bh[t].y);
            }
        }
    }
    #pragma unroll
    for (int m = 0; m < 2; m++)
        #pragma unroll
        for (int t = 0; t < 4; t++) {
            int col = warp * 32 + t * 8 + tq * 2;
            float bb0 = b2[col], bb1 = b2[col + 1];
            int r0 = m * 16 + g, r1 = m * 16 + 8 + g;
            float v00 = fmaxf(d[m][t][0] + bb0, 0.f), v01 = fmaxf(d[m][t][1] + bb1, 0.f);
            float v10 = fmaxf(d[m][t][2] + bb0, 0.f), v11 = fmaxf(d[m][t][3] + bb1, 0.f);
            __half x;
            x = __float2half(v00); h2h[r0 * 136 + col] = x; h2l[r0 * 136 + col] = __float2half(v00 - __half2float(x));
            x = __float2half(v01); h2h[r0 * 136 + col + 1] = x; h2l[r0 * 136 + col + 1] = __float2half(v01 - __half2float(x));
            x = __float2half(v10); h2h[r1 * 136 + col] = x; h2l[r1 * 136 + col] = __float2half(v10 - __half2float(x));
            x = __float2half(v11); h2h[r1 * 136 + col + 1] = x; h2l[r1 * 136 + col + 1] = __float2half(v11 - __half2float(x));
        }
    __syncthreads();

    // ---- layer 3: 128 -> 64 (2 m-tiles x 2 n-tiles/warp) ----
    #pragma unroll
    for (int m = 0; m < 2; m++)
        #pragma unroll
        for (int t = 0; t < 2; t++) { d[m][t][0] = d[m][t][1] = d[m][t][2] = d[m][t][3] = 0.f; }
    for (int kt = 0; kt < 8; kt++) {
        int k0 = kt * 16;
        uint2 bh[2], bl[2];
        #pragma unroll
        for (int t = 0; t < 2; t++) {
            int fi = ((kt * 8 + warp * 2 + t) << 5) + lane;
            bh[t] = __ldg(&g_w3f_h[fi]);
            bl[t] = __ldg(&g_w3f_l[fi]);
        }
        #pragma unroll
        for (int m = 0; m < 2; m++) {
            int r0 = m * 16 + g, r1 = m * 16 + 8 + g;
            u32 ah0 = *(const u32*)&h2h[r0 * 136 + k0 + tq * 2];
            u32 ah1 = *(const u32*)&h2h[r1 * 136 + k0 + tq * 2];
            u32 ah2 = *(const u32*)&h2h[r0 * 136 + k0 + 8 + tq * 2];
            u32 ah3 = *(const u32*)&h2h[r1 * 136 + k0 + 8 + tq * 2];
            u32 al0 = *(const u32*)&h2l[r0 * 136 + k0 + tq * 2];
            u32 al1 = *(const u32*)&h2l[r1 * 136 + k0 + tq * 2];
            u32 al2 = *(const u32*)&h2l[r0 * 136 + k0 + 8 + tq * 2];
            u32 al3 = *(const u32*)&h2l[r1 * 136 + k0 + 8 + tq * 2];
            #pragma unroll
            for (int t = 0; t < 2; t++) {
                mma16816(d[m][t], ah0, ah1, ah2, ah3, bh[t].x, bh[t].y);
                mma16816(d[m][t], ah0, ah1, ah2, ah3, bl[t].x, bl[t].y);
                mma16816(d[m][t], al0, al1, al2, al3, bh[t].x, bh[t].y);
            }
        }
    }
    #pragma unroll
    for (int m = 0; m < 2; m++)
        #pragma unroll
        for (int t = 0; t < 2; t++) {
            int col = warp * 16 + t * 8 + tq * 2;
            float bb0 = b3[col], bb1 = b3[col + 1];
            int r0 = m * 16 + g, r1 = m * 16 + 8 + g;
            h3s[r0 * 64 + col]     = fmaxf(d[m][t][0] + bb0, 0.f);
            h3s[r0 * 64 + col + 1] = fmaxf(d[m][t][1] + bb1, 0.f);
            h3s[r1 * 64 + col]     = fmaxf(d[m][t][2] + bb0, 0.f);
            h3s[r1 * 64 + col + 1] = fmaxf(d[m][t][3] + bb1, 0.f);
        }
    __syncthreads();

    // ---- layer 4: 64 -> 2, * scale (64 threads: 32 nodes x 2 outputs) ----
    if (tid < 64) {
        int nn = tid >> 1, o = tid & 1;
        int n = n0 + nn;
        if (n < N_NODES) {
            float a = b4[o];
            const float* wrow = &w4[o * 64];
            #pragma unroll 8
            for (int c = 0; c < 64; c++) a += h3s[nn * 64 + c] * wrow[c];
            out[(size_t)n * 2 + o] = a * scale[o];
        }
    }
}

// ---------------- launch ----------------
extern "C" void kernel_launch(void* const* d_in, const int* in_sizes, int n_in,
                              void* d_out, int out_size) {
    const float* x     = (const float*)d_in[0];
    const float* pos   = (const float*)d_in[1];
    const int*   ei    = (const int*)d_in[2];
    const float* W0    = (const float*)d_in[3];
    const float* Ws    = (const float*)d_in[4];
    const float* ln_g  = (const float*)d_in[5];
    const float* ln_b  = (const float*)d_in[6];
    const float* w1    = (const float*)d_in[7];
    const float* b1    = (const float*)d_in[8];
    const float* w2    = (const float*)d_in[9];
    const float* b2    = (const float*)d_in[10];
    const float* w3    = (const float*)d_in[11];
    const float* b3    = (const float*)d_in[12];
    const float* w4    = (const float*)d_in[13];
    const float* b4    = (const float*)d_in[14];
    const float* scale = (const float*)d_in[15];
    float* out = (float*)d_out;

    cudaFuncSetAttribute(k_mlp, cudaFuncAttributeMaxDynamicSharedMemorySize, SMEM_MLP);

    const int TGRID = (N_NODES + 31) / 32;  // 1563

    k_hist<<<(N_EDGES + 255) / 256, 256>>>(ei);                    // #1
    k_quant_prep<<<69, 256>>>(W0, Ws, w1, w2, w3);                 // #2
    k_scan_local<<<SCAN_BLK, 512>>>();                             // #3
    k_transform0<<<TGRID, 256>>>(x, pos);                          // #4  <- profiled
    k_scan_add<<<SCAN_BLK, 512>>>();                               // #5
    k_scatter<<<(N_EDGES + 255) / 256, 256>>>(ei);                 // #6
    k_aggregate<<<N_NODES / 16, 256>>>(pos, ln_g, ln_b, 0, 4);     // #7

    for (int i = 1; i < 5; i++) {
        k_transform<<<TGRID, 256>>>(pos, i);
        k_aggregate<<<N_NODES / 16, 256>>>(pos, ln_g, ln_b, i, 67);
    }

    k_mlp<<<TGRID, 128, SMEM_MLP>>>(b1, b2, b3, w4, b4, scale, out);
}